// round 4
// baseline (speedup 1.0000x reference)
#include <cuda_runtime.h>
#include <cuda_bf16.h>
#include <cstdint>
#include <cstddef>

#define SLEN   4096
#define HD     256
#define NG     1024      // 4*HD
#define EDIM   256
#define KTAGS  20
#define START_ID 18
#define STOP_ID  19
#define NCHUNK 64
#define CHUNK  64

// ---------------- scratch (device globals; no runtime allocation) ----------------
__device__ __align__(16) float g_zpre[2][SLEN][NG];        // W_ih@x + b ; dir1 time-reversed
__device__ __align__(16) float g_hs[2][SLEN][HD];          // h states at ORIGINAL time index
__device__ __align__(16) float g_feats[SLEN][KTAGS];       // emit scores
__device__ __align__(16) float g_P[NCHUNK][KTAGS][KTAGS];  // CRF chunk log-semiring products

// ---------------- PTX helpers ----------------
__device__ __forceinline__ unsigned smem_u32(const void* p) {
    return (unsigned)__cvta_generic_to_shared(p);
}
__device__ __forceinline__ void cluster_sync_() {
    asm volatile("barrier.cluster.arrive.aligned;" ::: "memory");
    asm volatile("barrier.cluster.wait.aligned;" ::: "memory");
}
__device__ __forceinline__ void mbar_init(unsigned a, unsigned cnt) {
    asm volatile("mbarrier.init.shared.b64 [%0], %1;" :: "r"(a), "r"(cnt) : "memory");
}
__device__ __forceinline__ void mbar_wait(unsigned a, unsigned parity) {
    asm volatile(
        "{\n\t"
        ".reg .pred P;\n\t"
        "WL%=:\n\t"
        "mbarrier.try_wait.parity.acquire.cluster.shared::cta.b64 P, [%0], %1, 0x989680;\n\t"
        "@P bra WD%=;\n\t"
        "bra WL%=;\n\t"
        "WD%=:\n\t"
        "}" :: "r"(a), "r"(parity) : "memory");
}
__device__ __forceinline__ void st_remote_f32(unsigned a, int rk, float v) {
    unsigned ra;
    asm volatile("mapa.shared::cluster.u32 %0, %1, %2;" : "=r"(ra) : "r"(a), "r"(rk));
    asm volatile("st.shared::cluster.f32 [%0], %1;" :: "r"(ra), "f"(v) : "memory");
}
__device__ __forceinline__ void arrive_remote(unsigned a, int rk) {
    unsigned ra;
    asm volatile("mapa.shared::cluster.u32 %0, %1, %2;" : "=r"(ra) : "r"(a), "r"(rk));
    asm volatile("mbarrier.arrive.release.cluster.shared::cluster.b64 _, [%0];" :: "r"(ra) : "memory");
}
__device__ __forceinline__ float fsigmoid(float x) {
    return __fdividef(1.f, 1.f + __expf(-x));      // robust: -inf->0, +inf->1
}
__device__ __forceinline__ float ftanh(float x) {
    return 1.f - __fdividef(2.f, __expf(2.f * x) + 1.f);  // robust at both ends
}

// =================================================================================
// Kernel 1: embedding gather + input projection:  zpre[d][t][g] = x_t . W_ih[g] + b[g]
// dir1 uses src_t = S-1-t (time-reversed) so the recurrent kernel is a plain loop.
// =================================================================================
__global__ void __launch_bounds__(256) pre_gemm(
    const int* __restrict__ sent, const float* __restrict__ embed,
    const float* __restrict__ w_f, const float* __restrict__ b_f,
    const float* __restrict__ w_b, const float* __restrict__ b_b)
{
    int bt  = blockIdx.x;            // 64 t-tiles of 64
    int br  = blockIdx.y;            // 32 = 2 dirs * 16 gate-row tiles of 64
    int dir = br >> 4;
    int r0  = (br & 15) * 64;
    const float* W  = dir ? w_b : w_f;
    const float* Bv = dir ? b_b : b_f;

    __shared__ float Xs[64][33];
    __shared__ float Ws[64][33];

    int tid = threadIdx.x;
    int tx = tid & 15, ty = tid >> 4;    // 16x16 threads, each computes 4x4
    float acc[4][4];
    #pragma unroll
    for (int i = 0; i < 4; i++)
        #pragma unroll
        for (int j = 0; j < 4; j++) acc[i][j] = 0.f;

    for (int k0 = 0; k0 < EDIM; k0 += 32) {
        for (int l = tid; l < 64 * 32; l += 256) {
            int row = l >> 5, kk = l & 31;
            int t = bt * 64 + row;
            int src_t = dir ? (SLEN - 1 - t) : t;
            Xs[row][kk] = embed[(size_t)sent[src_t] * EDIM + (k0 + kk)];
        }
        for (int l = tid; l < 64 * 32; l += 256) {
            int row = l >> 5, kk = l & 31;
            Ws[row][kk] = W[(size_t)(r0 + row) * EDIM + (k0 + kk)];
        }
        __syncthreads();
        #pragma unroll
        for (int kk = 0; kk < 32; kk++) {
            float av[4], bv[4];
            #pragma unroll
            for (int i = 0; i < 4; i++) av[i] = Xs[ty * 4 + i][kk];
            #pragma unroll
            for (int j = 0; j < 4; j++) bv[j] = Ws[tx * 4 + j][kk];
            #pragma unroll
            for (int i = 0; i < 4; i++)
                #pragma unroll
                for (int j = 0; j < 4; j++) acc[i][j] += av[i] * bv[j];
        }
        __syncthreads();
    }
    #pragma unroll
    for (int i = 0; i < 4; i++) {
        int t = bt * 64 + ty * 4 + i;
        #pragma unroll
        for (int j = 0; j < 4; j++) {
            int g = r0 + tx * 4 + j;
            g_zpre[dir][t][g] = acc[i][j] + Bv[g];
        }
    }
}

// =================================================================================
// Kernel 2: LSTM recurrence. 2 clusters of 8 CTAs (one per direction).
// CTA `rank` owns h-units [rank*32, rank*32+32); each thread owns one
// (unit, gate, k-segment-of-64) slice of W_hh, resident in 64 registers.
// Per step: dot(h) -> shfl reduce over 4 k-segs -> gate combine by 32 unit
// threads -> broadcast 32 h values to all 8 CTAs via DSMEM + mbarrier.
// Exit safety: no remote store/arrive at the final step; trailing cluster sync
// so no CTA departs while a peer could still target its SMEM.
// =================================================================================
__global__ void __launch_bounds__(512, 1) __cluster_dims__(8, 1, 1)
lstm_rec(const float* __restrict__ w_hh_f, const float* __restrict__ w_hh_b,
         const float* __restrict__ h0, const float* __restrict__ c0)
{
    __shared__ __align__(16) float hbuf[2][HD];
    __shared__ float zg_s[32][4];
    __shared__ __align__(8) unsigned long long mbar[2];

    int tid  = threadIdx.x;
    int cta  = blockIdx.x;
    int dir  = cta >> 3;
    int rank = cta & 7;
    const float* W = dir ? w_hh_b : w_hh_f;

    int lu = tid >> 4;            // local unit 0..31
    int q  = (tid >> 2) & 3;      // gate: 0=i 1=f 2=g 3=o
    int ks = tid & 3;             // k-segment of 64
    int u  = rank * 32 + lu;      // global h-unit
    int grow = q * 256 + u;       // gate row in [0,1024)

    // resident weights: 64 floats (16 float4)
    float4 w[16];
    {
        const float4* Wrow = (const float4*)(W + (size_t)grow * HD + ks * 64);
        #pragma unroll
        for (int m = 0; m < 16; m++) w[m] = Wrow[m];
    }

    if (tid == 0) {
        mbar_init(smem_u32(&mbar[0]), 256);   // 8 CTAs * 32 unit-thread arrivals
        mbar_init(smem_u32(&mbar[1]), 256);
    }
    if (tid < HD) hbuf[0][tid] = h0[dir * HD + tid];
    float c = 0.f;
    if (tid < 32) c = c0[dir * HD + rank * 32 + tid];
    cluster_sync_();   // mbarriers + hbuf[0] visible cluster-wide

    unsigned mb[2] = { smem_u32(&mbar[0]), smem_u32(&mbar[1]) };
    unsigned ph[2] = { 0u, 0u };
    const float* zbase = &g_zpre[dir][0][0];

    for (int t = 0; t < SLEN; t++) {
        int b = t & 1;
        // prefetch zpre for this step (LDG overlaps the barrier wait)
        float zpre = 0.f;
        if (ks == 0) zpre = zbase[(size_t)t * NG + grow];

        if (t > 0) { mbar_wait(mb[b], ph[b]); ph[b] ^= 1; }

        // partial dot over this thread's 64 h values
        const float4* h4 = (const float4*)&hbuf[b][ks * 64];
        float acc = 0.f;
        #pragma unroll
        for (int m = 0; m < 16; m++) {
            float4 hv = h4[m];
            acc += w[m].x * hv.x + w[m].y * hv.y + w[m].z * hv.z + w[m].w * hv.w;
        }
        acc += __shfl_xor_sync(0xFFFFFFFFu, acc, 1);
        acc += __shfl_xor_sync(0xFFFFFFFFu, acc, 2);
        if (ks == 0) zg_s[lu][q] = acc + zpre;
        __syncthreads();

        if (tid < 32) {
            float zi = zg_s[tid][0], zf = zg_s[tid][1];
            float zgv = zg_s[tid][2], zo = zg_s[tid][3];
            c = fsigmoid(zf) * c + fsigmoid(zi) * ftanh(zgv);
            float h = fsigmoid(zo) * ftanh(c);
            int uu = rank * 32 + tid;
            int orig_t = dir ? (SLEN - 1 - t) : t;
            g_hs[dir][orig_t][uu] = h;
            if (t < SLEN - 1) {   // final step: nobody consumes; avoid remote ops at exit
                int nb = b ^ 1;
                unsigned haddr = smem_u32(&hbuf[nb][uu]);
                #pragma unroll
                for (int p = 0; p < 8; p++) st_remote_f32(haddr, p, h);
                #pragma unroll
                for (int p = 0; p < 8; p++) arrive_remote(mb[nb], p);
            }
        }
        // zg_s/hbuf reuse at t+1 is gated by mbar[nb]: it completes only after
        // every CTA's unit threads arrived, which happens after their CTA's
        // __syncthreads() — i.e. after all 512 threads finished reading hbuf[b].
    }
    // No CTA may exit while a peer could still address its SMEM.
    cluster_sync_();
}

// =================================================================================
// Kernel 3: emit features  feats[t][k] = [h_f | h_b] . emit_W[k] + emit_b[k]
// =================================================================================
__global__ void __launch_bounds__(256) emit_k(
    const float* __restrict__ emit_W, const float* __restrict__ emit_b)
{
    int idx = blockIdx.x * blockDim.x + threadIdx.x;
    if (idx >= SLEN * KTAGS) return;
    int t = idx / KTAGS, k = idx % KTAGS;
    const float4* hf = (const float4*)&g_hs[0][t][0];
    const float4* hb = (const float4*)&g_hs[1][t][0];
    const float4* wf = (const float4*)&emit_W[(size_t)k * 512];
    const float4* wb = wf + 64;
    float acc = emit_b[k];
    #pragma unroll 8
    for (int m = 0; m < 64; m++) {
        float4 h = hf[m], ww = wf[m];
        acc += h.x * ww.x + h.y * ww.y + h.z * ww.z + h.w * ww.w;
    }
    #pragma unroll 8
    for (int m = 0; m < 64; m++) {
        float4 h = hb[m], ww = wb[m];
        acc += h.x * ww.x + h.y * ww.y + h.z * ww.z + h.w * ww.w;
    }
    g_feats[t][k] = acc;
}

// =================================================================================
// Kernel 4: CRF chunk fold. fv' = M_t (*) fv with M_t[i][j] = trans[i][j]+feat[t][i]
// is a log-semiring matvec => associative. Each block folds 64 steps into a
// 20x20 matrix P_c (log-semiring product of its M_t's).
// =================================================================================
__global__ void __launch_bounds__(512) crf_chunks(const float* __restrict__ trans)
{
    __shared__ float Ts[KTAGS][KTAGS], C[KTAGS][KTAGS], fe[KTAGS];
    int tid = threadIdx.x;
    int cix = blockIdx.x;
    int t0 = cix * CHUNK;

    if (tid < 400) Ts[tid / 20][tid % 20] = trans[tid];
    if (tid < KTAGS) fe[tid] = g_feats[t0][tid];
    __syncthreads();
    if (tid < 400) {
        int i = tid / 20, j = tid % 20;
        C[i][j] = Ts[i][j] + fe[i];
    }
    __syncthreads();

    for (int t = t0 + 1; t < t0 + CHUNK; t++) {
        if (tid < KTAGS) fe[tid] = g_feats[t][tid];
        __syncthreads();
        float v = 0.f;
        if (tid < 400) {
            int i = tid / 20, k = tid % 20;
            float m = -1e30f;
            #pragma unroll
            for (int j = 0; j < KTAGS; j++) m = fmaxf(m, Ts[i][j] + C[j][k]);
            float s = 0.f;
            #pragma unroll
            for (int j = 0; j < KTAGS; j++) s += __expf(Ts[i][j] + C[j][k] - m);
            v = fe[i] + m + __logf(s);
        }
        __syncthreads();
        if (tid < 400) C[tid / 20][tid % 20] = v;
        __syncthreads();
    }
    if (tid < 400) g_P[cix][tid / 20][tid % 20] = C[tid / 20][tid % 20];
}

// =================================================================================
// Kernel 5: sequential chunk combine (64 log-semiring matvecs) + gold score.
// =================================================================================
__global__ void __launch_bounds__(512) crf_final(
    const float* __restrict__ trans, const int* __restrict__ tags,
    float* __restrict__ out)
{
    __shared__ float fv[KTAGS], nv[KTAGS], red[512];
    int tid = threadIdx.x;

    // gold path partial sums (deterministic tree reduce)
    float part = 0.f;
    for (int t = tid; t < SLEN; t += 512) {
        int tg = tags[t];
        int pv = (t == 0) ? START_ID : tags[t - 1];
        part += trans[tg * KTAGS + pv] + g_feats[t][tg];
    }
    red[tid] = part;
    __syncthreads();
    for (int s = 256; s > 0; s >>= 1) {
        if (tid < s) red[tid] += red[tid + s];
        __syncthreads();
    }

    if (tid < KTAGS) fv[tid] = (tid == START_ID) ? 0.f : -10000.f;
    __syncthreads();
    for (int cix = 0; cix < NCHUNK; cix++) {
        if (tid < KTAGS) {
            float m = -1e30f;
            #pragma unroll
            for (int j = 0; j < KTAGS; j++) m = fmaxf(m, g_P[cix][tid][j] + fv[j]);
            float s = 0.f;
            #pragma unroll
            for (int j = 0; j < KTAGS; j++) s += __expf(g_P[cix][tid][j] + fv[j] - m);
            nv[tid] = m + __logf(s);
        }
        __syncthreads();
        if (tid < KTAGS) fv[tid] = nv[tid];
        __syncthreads();
    }
    if (tid == 0) {
        float m = -1e30f, s = 0.f;
        #pragma unroll
        for (int i = 0; i < KTAGS; i++) m = fmaxf(m, fv[i] + trans[STOP_ID * KTAGS + i]);
        #pragma unroll
        for (int i = 0; i < KTAGS; i++) s += __expf(fv[i] + trans[STOP_ID * KTAGS + i] - m);
        out[0] = m + __logf(s);
        out[1] = red[0] + trans[STOP_ID * KTAGS + tags[SLEN - 1]];
    }
}

// =================================================================================
extern "C" void kernel_launch(void* const* d_in, const int* in_sizes, int n_in,
                              void* d_out, int out_size)
{
    const int*   sent    = (const int*)d_in[0];
    const int*   tags    = (const int*)d_in[1];
    const float* embed   = (const float*)d_in[2];
    const float* w_ih_f  = (const float*)d_in[3];
    const float* w_hh_f  = (const float*)d_in[4];
    const float* b_f     = (const float*)d_in[5];
    const float* w_ih_b  = (const float*)d_in[6];
    const float* w_hh_b  = (const float*)d_in[7];
    const float* b_b     = (const float*)d_in[8];
    const float* h0      = (const float*)d_in[9];
    const float* c0      = (const float*)d_in[10];
    const float* emit_W  = (const float*)d_in[11];
    const float* emit_b  = (const float*)d_in[12];
    const float* trans   = (const float*)d_in[13];
    float* out = (float*)d_out;

    pre_gemm<<<dim3(64, 32), 256>>>(sent, embed, w_ih_f, b_f, w_ih_b, b_b);
    lstm_rec<<<16, 512>>>(w_hh_f, w_hh_b, h0, c0);
    emit_k<<<(SLEN * KTAGS + 255) / 256, 256>>>(emit_W, emit_b);
    crf_chunks<<<NCHUNK, 512>>>(trans);
    crf_final<<<1, 512>>>(trans, tags, out);
}

// round 8
// speedup vs baseline: 2.6070x; 2.6070x over previous
#include <cuda_runtime.h>
#include <cuda_bf16.h>
#include <cstdint>
#include <cstddef>

#define SLEN   4096
#define HD     256
#define NG     1024      // 4*HD
#define EDIM   256
#define KTAGS  20
#define START_ID 18
#define STOP_ID  19
#define NCHUNK 64
#define CHUNK  64

// padded h layout: 4 segments of 64 floats, +4 floats pad between segments
#define SEGW   68
#define HBUFW  (4 * SEGW)   // 272 floats per buffer

// ---------------- scratch (device globals; no runtime allocation) ----------------
__device__ __align__(16) float g_zpre[2][SLEN][NG];        // W_ih@x + b ; dir1 time-reversed
__device__ __align__(16) float g_hs[2][SLEN][HD];          // h states at ORIGINAL time index
__device__ __align__(16) float g_feats[SLEN][KTAGS];       // emit scores
__device__ __align__(16) float g_P[NCHUNK][KTAGS][KTAGS];  // CRF chunk log-semiring products

// ---------------- PTX helpers (R4-proven instruction set only) ----------------
__device__ __forceinline__ unsigned smem_u32(const void* p) {
    return (unsigned)__cvta_generic_to_shared(p);
}
__device__ __forceinline__ void cluster_sync_() {
    asm volatile("barrier.cluster.arrive.aligned;" ::: "memory");
    asm volatile("barrier.cluster.wait.aligned;" ::: "memory");
}
__device__ __forceinline__ void mbar_init(unsigned a, unsigned cnt) {
    asm volatile("mbarrier.init.shared.b64 [%0], %1;" :: "r"(a), "r"(cnt) : "memory");
}
// cluster-scope acquire wait — exactly the wait R4 passed with.
__device__ __forceinline__ void mbar_wait_cluster(unsigned a, unsigned parity) {
    asm volatile(
        "{\n\t"
        ".reg .pred P;\n\t"
        "WL%=:\n\t"
        "mbarrier.try_wait.parity.acquire.cluster.shared::cta.b64 P, [%0], %1, 0x989680;\n\t"
        "@P bra WD%=;\n\t"
        "bra WL%=;\n\t"
        "WD%=:\n\t"
        "}" :: "r"(a), "r"(parity) : "memory");
}
__device__ __forceinline__ unsigned mapa_sc(unsigned a, int rk) {
    unsigned ra;
    asm volatile("mapa.shared::cluster.u32 %0, %1, %2;" : "=r"(ra) : "r"(a), "r"(rk));
    return ra;
}
__device__ __forceinline__ void st_remote_v4(unsigned ra, float4 v) {
    asm volatile("st.shared::cluster.v4.f32 [%0], {%1, %2, %3, %4};"
                 :: "r"(ra), "f"(v.x), "f"(v.y), "f"(v.z), "f"(v.w) : "memory");
}
__device__ __forceinline__ void arrive_release_at(unsigned ra) {
    asm volatile("mbarrier.arrive.release.cluster.shared::cluster.b64 _, [%0];"
                 :: "r"(ra) : "memory");
}
__device__ __forceinline__ unsigned long long fma2_(unsigned long long a,
                                                    unsigned long long b,
                                                    unsigned long long c) {
    unsigned long long d;
    asm("fma.rn.f32x2 %0, %1, %2, %3;" : "=l"(d) : "l"(a), "l"(b), "l"(c));
    return d;
}
__device__ __forceinline__ float f2_sum(unsigned long long a) {
    unsigned lo, hi;
    asm("mov.b64 {%0, %1}, %2;" : "=r"(lo), "=r"(hi) : "l"(a));
    return __uint_as_float(lo) + __uint_as_float(hi);
}
__device__ __forceinline__ float fsigmoid(float x) {
    return __fdividef(1.f, 1.f + __expf(-x));      // robust: -inf->0, +inf->1
}
__device__ __forceinline__ float ftanh(float x) {
    return 1.f - __fdividef(2.f, __expf(2.f * x) + 1.f);  // robust at both ends
}

// =================================================================================
// Kernel 1: embedding gather + input projection:  zpre[d][t][g] = x_t . W_ih[g] + b[g]
// dir1 uses src_t = S-1-t (time-reversed) so the recurrent kernel is a plain loop.
// =================================================================================
__global__ void __launch_bounds__(256) pre_gemm(
    const int* __restrict__ sent, const float* __restrict__ embed,
    const float* __restrict__ w_f, const float* __restrict__ b_f,
    const float* __restrict__ w_b, const float* __restrict__ b_b)
{
    int bt  = blockIdx.x;            // 64 t-tiles of 64
    int br  = blockIdx.y;            // 32 = 2 dirs * 16 gate-row tiles of 64
    int dir = br >> 4;
    int r0  = (br & 15) * 64;
    const float* W  = dir ? w_b : w_f;
    const float* Bv = dir ? b_b : b_f;

    __shared__ float Xs[64][33];
    __shared__ float Ws[64][33];

    int tid = threadIdx.x;
    int tx = tid & 15, ty = tid >> 4;    // 16x16 threads, each computes 4x4
    float acc[4][4];
    #pragma unroll
    for (int i = 0; i < 4; i++)
        #pragma unroll
        for (int j = 0; j < 4; j++) acc[i][j] = 0.f;

    for (int k0 = 0; k0 < EDIM; k0 += 32) {
        for (int l = tid; l < 64 * 32; l += 256) {
            int row = l >> 5, kk = l & 31;
            int t = bt * 64 + row;
            int src_t = dir ? (SLEN - 1 - t) : t;
            Xs[row][kk] = embed[(size_t)sent[src_t] * EDIM + (k0 + kk)];
        }
        for (int l = tid; l < 64 * 32; l += 256) {
            int row = l >> 5, kk = l & 31;
            Ws[row][kk] = W[(size_t)(r0 + row) * EDIM + (k0 + kk)];
        }
        __syncthreads();
        #pragma unroll
        for (int kk = 0; kk < 32; kk++) {
            float av[4], bv[4];
            #pragma unroll
            for (int i = 0; i < 4; i++) av[i] = Xs[ty * 4 + i][kk];
            #pragma unroll
            for (int j = 0; j < 4; j++) bv[j] = Ws[tx * 4 + j][kk];
            #pragma unroll
            for (int i = 0; i < 4; i++)
                #pragma unroll
                for (int j = 0; j < 4; j++) acc[i][j] += av[i] * bv[j];
        }
        __syncthreads();
    }
    #pragma unroll
    for (int i = 0; i < 4; i++) {
        int t = bt * 64 + ty * 4 + i;
        #pragma unroll
        for (int j = 0; j < 4; j++) {
            int g = r0 + tx * 4 + j;
            g_zpre[dir][t][g] = acc[i][j] + Bv[g];
        }
    }
}

// =================================================================================
// Kernel 2: LSTM recurrence. 2 clusters of 8 CTAs (one per direction).
// CTA `rank` owns h-units [rank*32, rank*32+32); each thread owns one
// (unit, gate, k-segment-of-64) slice of W_hh resident in registers as f32x2.
// Broadcast (R4-proven primitives, restructured for issue efficiency):
//   unit warp stages 32 h floats locally; lane p (p<8) copies all 32 floats to
//   peer p via 8 x st.shared::cluster.v4.f32, then one release-arrive on peer
//   p's mbarrier (count=8: one arrive per peer).
// Consumer: ONLY tid0 does the cluster-acquire try_wait; __syncthreads()
//   propagates visibility to the whole CTA (arrive.release -> acquire -> bar).
// =================================================================================
__global__ void __launch_bounds__(512, 1) __cluster_dims__(8, 1, 1)
lstm_rec(const float* __restrict__ w_hh_f, const float* __restrict__ w_hh_b,
         const float* __restrict__ h0, const float* __restrict__ c0)
{
    __shared__ __align__(16) float hbuf[2][HBUFW];   // padded: off = (u>>6)*68 + (u&63)
    __shared__ __align__(16) float hstage[32];       // this CTA's 32 h values, per step
    __shared__ float zg_s[32][4];
    __shared__ __align__(8) unsigned long long mbar[2];

    int tid  = threadIdx.x;
    int cta  = blockIdx.x;
    int dir  = cta >> 3;
    int rank = cta & 7;
    const float* W = dir ? w_hh_b : w_hh_f;

    int lu = tid >> 4;            // local unit 0..31
    int q  = (tid >> 2) & 3;      // gate: 0=i 1=f 2=g 3=o
    int ks = tid & 3;             // k-segment of 64
    int u  = rank * 32 + lu;      // global h-unit
    int grow = q * 256 + u;       // gate row in [0,1024)

    // resident weights: 64 floats packed as 32 f32x2 (16 ulonglong2 loads)
    unsigned long long wx[16], wy[16];
    {
        const ulonglong2* Wrow = (const ulonglong2*)(W + (size_t)grow * HD + ks * 64);
        #pragma unroll
        for (int m = 0; m < 16; m++) { ulonglong2 v = Wrow[m]; wx[m] = v.x; wy[m] = v.y; }
    }

    unsigned mb0 = smem_u32(&mbar[0]);
    unsigned mb1 = smem_u32(&mbar[1]);
    if (tid == 0) {
        mbar_init(mb0, 8);   // one arrive per peer CTA per phase
        mbar_init(mb1, 8);
    }
    if (tid < HD) hbuf[0][(tid >> 6) * SEGW + (tid & 63)] = h0[dir * HD + tid];
    float c = 0.f;
    if (tid < 32) c = c0[dir * HD + rank * 32 + tid];
    cluster_sync_();   // mbarriers + hbuf[0] visible cluster-wide

    // lane p (<8): base of OUR 32-float slot inside peer p's hbuf[0]/[1] + its mbars
    unsigned dstb0 = 0, dstb1 = 0, pm0 = 0, pm1 = 0;
    if (tid < 8) {
        unsigned slot = smem_u32(&hbuf[0][(rank >> 1) * SEGW + (rank & 1) * 32]);
        dstb0 = mapa_sc(slot, tid);
        dstb1 = mapa_sc(slot + HBUFW * 4, tid);   // hbuf[1] is +HBUFW floats
        pm0   = mapa_sc(mb0, tid);
        pm1   = mapa_sc(mb1, tid);
    }

    unsigned mbl[2] = { mb0, mb1 };
    unsigned ph[2]  = { 0u, 0u };
    const float* zbase = &g_zpre[dir][0][0];

    for (int t = 0; t < SLEN; t++) {
        int b = t & 1;
        // prefetch zpre for this step (LDG overlaps the wait)
        float zpre = 0.f;
        if (ks == 0) zpre = zbase[(size_t)t * NG + grow];

        if (t > 0) {
            if (tid == 0) mbar_wait_cluster(mbl[b], ph[b]);
            ph[b] ^= 1;
            __syncthreads();   // releases the CTA with peer writes visible
        }

        // partial dot over this thread's 64 h values (f32x2 FMA)
        const ulonglong2* h8 = (const ulonglong2*)&hbuf[b][ks * SEGW];
        unsigned long long a0 = 0ULL, a1 = 0ULL;
        #pragma unroll
        for (int m = 0; m < 16; m++) {
            ulonglong2 hv = h8[m];
            a0 = fma2_(wx[m], hv.x, a0);
            a1 = fma2_(wy[m], hv.y, a1);
        }
        float acc = f2_sum(a0) + f2_sum(a1);
        acc += __shfl_xor_sync(0xFFFFFFFFu, acc, 1);
        acc += __shfl_xor_sync(0xFFFFFFFFu, acc, 2);
        if (ks == 0) zg_s[lu][q] = acc + zpre;
        __syncthreads();

        if (tid < 32) {
            float zi = zg_s[tid][0], zf = zg_s[tid][1];
            float zgv = zg_s[tid][2], zo = zg_s[tid][3];
            c = fsigmoid(zf) * c + fsigmoid(zi) * ftanh(zgv);
            float h = fsigmoid(zo) * ftanh(c);
            hstage[tid] = h;
            int orig_t = dir ? (SLEN - 1 - t) : t;
            g_hs[dir][orig_t][rank * 32 + tid] = h;
            __syncwarp();                        // hstage complete for lane reads
            if (t < SLEN - 1 && tid < 8) {       // final step: nobody consumes
                unsigned dst = (b ^ 1) ? dstb1 : dstb0;
                unsigned pm  = (b ^ 1) ? pm1  : pm0;
                #pragma unroll
                for (int m = 0; m < 8; m++) {
                    float4 v = *(const float4*)&hstage[m * 4];
                    st_remote_v4(dst + m * 16, v);
                }
                arrive_release_at(pm);           // releases this lane's 8 stores
            }
        }
        // Overwrite safety (same invariant R4 ran with): mbar[b]'s next phase
        // completes only after every CTA passed its step-t post-dot barrier,
        // i.e. after all reads of hbuf[b]; hstage rewrite at t+1 is ordered by
        // the two __syncthreads in between.
    }
    // No CTA may exit while a peer could still address its SMEM.
    cluster_sync_();
}

// =================================================================================
// Kernel 3: emit features  feats[t][k] = [h_f | h_b] . emit_W[k] + emit_b[k]
// =================================================================================
__global__ void __launch_bounds__(256) emit_k(
    const float* __restrict__ emit_W, const float* __restrict__ emit_b)
{
    int idx = blockIdx.x * blockDim.x + threadIdx.x;
    if (idx >= SLEN * KTAGS) return;
    int t = idx / KTAGS, k = idx % KTAGS;
    const float4* hf = (const float4*)&g_hs[0][t][0];
    const float4* hb = (const float4*)&g_hs[1][t][0];
    const float4* wf = (const float4*)&emit_W[(size_t)k * 512];
    const float4* wb = wf + 64;
    float acc = emit_b[k];
    #pragma unroll 8
    for (int m = 0; m < 64; m++) {
        float4 h = hf[m], ww = wf[m];
        acc += h.x * ww.x + h.y * ww.y + h.z * ww.z + h.w * ww.w;
    }
    #pragma unroll 8
    for (int m = 0; m < 64; m++) {
        float4 h = hb[m], ww = wb[m];
        acc += h.x * ww.x + h.y * ww.y + h.z * ww.z + h.w * ww.w;
    }
    g_feats[t][k] = acc;
}

// =================================================================================
// Kernel 4: CRF chunk fold. fv' = M_t (*) fv with M_t[i][j] = trans[i][j]+feat[t][i]
// is a log-semiring matvec => associative. Each block folds 64 steps into a
// 20x20 matrix P_c (log-semiring product of its M_t's).
// =================================================================================
__global__ void __launch_bounds__(512) crf_chunks(const float* __restrict__ trans)
{
    __shared__ float Ts[KTAGS][KTAGS], C[KTAGS][KTAGS], fe[KTAGS];
    int tid = threadIdx.x;
    int cix = blockIdx.x;
    int t0 = cix * CHUNK;

    if (tid < 400) Ts[tid / 20][tid % 20] = trans[tid];
    if (tid < KTAGS) fe[tid] = g_feats[t0][tid];
    __syncthreads();
    if (tid < 400) {
        int i = tid / 20, j = tid % 20;
        C[i][j] = Ts[i][j] + fe[i];
    }
    __syncthreads();

    for (int t = t0 + 1; t < t0 + CHUNK; t++) {
        if (tid < KTAGS) fe[tid] = g_feats[t][tid];
        __syncthreads();
        float v = 0.f;
        if (tid < 400) {
            int i = tid / 20, k = tid % 20;
            float m = -1e30f;
            #pragma unroll
            for (int j = 0; j < KTAGS; j++) m = fmaxf(m, Ts[i][j] + C[j][k]);
            float s = 0.f;
            #pragma unroll
            for (int j = 0; j < KTAGS; j++) s += __expf(Ts[i][j] + C[j][k] - m);
            v = fe[i] + m + __logf(s);
        }
        __syncthreads();
        if (tid < 400) C[tid / 20][tid % 20] = v;
        __syncthreads();
    }
    if (tid < 400) g_P[cix][tid / 20][tid % 20] = C[tid / 20][tid % 20];
}

// =================================================================================
// Kernel 5: sequential chunk combine (64 log-semiring matvecs) + gold score.
// =================================================================================
__global__ void __launch_bounds__(512) crf_final(
    const float* __restrict__ trans, const int* __restrict__ tags,
    float* __restrict__ out)
{
    __shared__ float fv[KTAGS], nv[KTAGS], red[512];
    int tid = threadIdx.x;

    // gold path partial sums (deterministic tree reduce)
    float part = 0.f;
    for (int t = tid; t < SLEN; t += 512) {
        int tg = tags[t];
        int pv = (t == 0) ? START_ID : tags[t - 1];
        part += trans[tg * KTAGS + pv] + g_feats[t][tg];
    }
    red[tid] = part;
    __syncthreads();
    for (int s = 256; s > 0; s >>= 1) {
        if (tid < s) red[tid] += red[tid + s];
        __syncthreads();
    }

    if (tid < KTAGS) fv[tid] = (tid == START_ID) ? 0.f : -10000.f;
    __syncthreads();
    for (int cix = 0; cix < NCHUNK; cix++) {
        if (tid < KTAGS) {
            float m = -1e30f;
            #pragma unroll
            for (int j = 0; j < KTAGS; j++) m = fmaxf(m, g_P[cix][tid][j] + fv[j]);
            float s = 0.f;
            #pragma unroll
            for (int j = 0; j < KTAGS; j++) s += __expf(g_P[cix][tid][j] + fv[j] - m);
            nv[tid] = m + __logf(s);
        }
        __syncthreads();
        if (tid < KTAGS) fv[tid] = nv[tid];
        __syncthreads();
    }
    if (tid == 0) {
        float m = -1e30f, s = 0.f;
        #pragma unroll
        for (int i = 0; i < KTAGS; i++) m = fmaxf(m, fv[i] + trans[STOP_ID * KTAGS + i]);
        #pragma unroll
        for (int i = 0; i < KTAGS; i++) s += __expf(fv[i] + trans[STOP_ID * KTAGS + i] - m);
        out[0] = m + __logf(s);
        out[1] = red[0] + trans[STOP_ID * KTAGS + tags[SLEN - 1]];
    }
}

// =================================================================================
extern "C" void kernel_launch(void* const* d_in, const int* in_sizes, int n_in,
                              void* d_out, int out_size)
{
    const int*   sent    = (const int*)d_in[0];
    const int*   tags    = (const int*)d_in[1];
    const float* embed   = (const float*)d_in[2];
    const float* w_ih_f  = (const float*)d_in[3];
    const float* w_hh_f  = (const float*)d_in[4];
    const float* b_f     = (const float*)d_in[5];
    const float* w_ih_b  = (const float*)d_in[6];
    const float* w_hh_b  = (const float*)d_in[7];
    const float* b_b     = (const float*)d_in[8];
    const float* h0      = (const float*)d_in[9];
    const float* c0      = (const float*)d_in[10];
    const float* emit_W  = (const float*)d_in[11];
    const float* emit_b  = (const float*)d_in[12];
    const float* trans   = (const float*)d_in[13];
    float* out = (float*)d_out;

    pre_gemm<<<dim3(64, 32), 256>>>(sent, embed, w_ih_f, b_f, w_ih_b, b_b);
    lstm_rec<<<16, 512>>>(w_hh_f, w_hh_b, h0, c0);
    emit_k<<<(SLEN * KTAGS + 255) / 256, 256>>>(emit_W, emit_b);
    crf_chunks<<<NCHUNK, 512>>>(trans);
    crf_final<<<1, 512>>>(trans, tags, out);
}